// round 1
// baseline (speedup 1.0000x reference)
#include <cuda_runtime.h>

// Clifford product in Cl(3,0), basis order: 1, e1, e2, e3, e12, e13, e23, e123
// (matching the reference's basis = [(), (0,), (1,), (2,), (0,1), (0,2), (1,2), (0,1,2)])
//
// Hardcoded Cayley table (derived from the reference's bubble-sort sign
// algorithm with e_k^2 = +1):
//   c0 = a0b0 + a1b1 + a2b2 + a3b3 - a4b4 - a5b5 - a6b6 - a7b7
//   c1 = a0b1 + a1b0 - a2b4 - a3b5 + a4b2 + a5b3 - a6b7 - a7b6
//   c2 = a0b2 + a1b4 + a2b0 - a3b6 - a4b1 + a5b7 + a6b3 + a7b5
//   c3 = a0b3 + a1b5 + a2b6 + a3b0 - a4b7 - a5b1 - a6b2 - a7b4
//   c4 = a0b4 + a1b2 - a2b1 + a3b7 + a4b0 - a5b6 + a6b5 + a7b3
//   c5 = a0b5 + a1b3 - a2b7 - a3b1 + a4b6 + a5b0 - a6b4 - a7b2
//   c6 = a0b6 + a1b7 + a2b3 - a3b2 - a4b5 + a5b4 + a6b0 + a7b1
//   c7 = a0b7 + a1b6 - a2b5 + a3b4 + a4b3 - a5b2 + a6b1 + a7b0
//
// Memory-bound: 96 B/element * 4M elements = 402 MB; floor ~50 us on 8 TB/s HBM3e.

__global__ void __launch_bounds__(256)
CliffordProduct_85452669321821_kernel(const float4* __restrict__ a,
                                      const float4* __restrict__ b,
                                      float4* __restrict__ out,
                                      int n) {
    int idx = blockIdx.x * blockDim.x + threadIdx.x;
    if (idx >= n) return;

    const float4 alo = a[2 * idx];
    const float4 ahi = a[2 * idx + 1];
    const float4 blo = b[2 * idx];
    const float4 bhi = b[2 * idx + 1];

    const float a0 = alo.x, a1 = alo.y, a2 = alo.z, a3 = alo.w;
    const float a4 = ahi.x, a5 = ahi.y, a6 = ahi.z, a7 = ahi.w;
    const float b0 = blo.x, b1 = blo.y, b2 = blo.z, b3 = blo.w;
    const float b4 = bhi.x, b5 = bhi.y, b6 = bhi.z, b7 = bhi.w;

    float4 clo, chi;
    clo.x = a0*b0 + a1*b1 + a2*b2 + a3*b3 - a4*b4 - a5*b5 - a6*b6 - a7*b7;
    clo.y = a0*b1 + a1*b0 - a2*b4 - a3*b5 + a4*b2 + a5*b3 - a6*b7 - a7*b6;
    clo.z = a0*b2 + a1*b4 + a2*b0 - a3*b6 - a4*b1 + a5*b7 + a6*b3 + a7*b5;
    clo.w = a0*b3 + a1*b5 + a2*b6 + a3*b0 - a4*b7 - a5*b1 - a6*b2 - a7*b4;
    chi.x = a0*b4 + a1*b2 - a2*b1 + a3*b7 + a4*b0 - a5*b6 + a6*b5 + a7*b3;
    chi.y = a0*b5 + a1*b3 - a2*b7 - a3*b1 + a4*b6 + a5*b0 - a6*b4 - a7*b2;
    chi.z = a0*b6 + a1*b7 + a2*b3 - a3*b2 - a4*b5 + a5*b4 + a6*b0 + a7*b1;
    chi.w = a0*b7 + a1*b6 - a2*b5 + a3*b4 + a4*b3 - a5*b2 + a6*b1 + a7*b0;

    out[2 * idx]     = clo;
    out[2 * idx + 1] = chi;
}

extern "C" void kernel_launch(void* const* d_in, const int* in_sizes, int n_in,
                              void* d_out, int out_size) {
    const float4* a = (const float4*)d_in[0];
    const float4* b = (const float4*)d_in[1];
    float4* out = (float4*)d_out;

    const int n = in_sizes[0] / 8;  // number of multivectors
    const int threads = 256;
    const int blocks = (n + threads - 1) / threads;
    CliffordProduct_85452669321821_kernel<<<blocks, threads>>>(a, b, out, n);
}